// round 1
// baseline (speedup 1.0000x reference)
#include <cuda_runtime.h>
#include <cuda_bf16.h>
#include <math.h>

#define NB 32
#define NN 512

// Scratch: c matrix (antisymmetrized pairwise net output) and G = c @ a
__device__ float g_c[(size_t)NB * NN * NN];
__device__ float g_G[(size_t)NB * NN * NN];

// temp arrives as a 1-elem scalar; could be int32 or float32 bits. Decode robustly:
// small ints reinterpreted as float are denormals (|f| < 1e-30) -> take int path.
__device__ __forceinline__ float decode_scalar(const int* p) {
    int ib = *p;
    float f = __int_as_float(ib);
    if (isfinite(f) && fabsf(f) > 1e-30f && fabsf(f) < 1e30f) return f;
    return (float)ib;
}

// ---------------------------------------------------------------------------
// c[b,i,j] = sum_o w2[o] * (relu(w1[o,0]*xi + w1[o,1]*xj + b1[o])
//                         - relu(w1[o,0]*xj + w1[o,1]*xi + b1[o]))
// (b2 cancels in the antisymmetrization)
// ---------------------------------------------------------------------------
__global__ void __launch_bounds__(256) compute_c_kernel(
    const float* __restrict__ x, const float* __restrict__ w1,
    const float* __restrict__ b1, const float* __restrict__ w2)
{
    int b = blockIdx.y;
    int i = blockIdx.x;
    __shared__ float xs[NN];
    __shared__ float sw1a[16], sw1b[16], sb1[16], sw2[16];
    int t = threadIdx.x;
    if (t < 16) {
        sw1a[t] = w1[t * 2 + 0];
        sw1b[t] = w1[t * 2 + 1];
        sb1[t]  = b1[t];
        sw2[t]  = w2[t];
    }
    xs[t]       = x[b * NN + t];
    xs[t + 256] = x[b * NN + t + 256];
    __syncthreads();

    float xi = xs[i];
    float* crow = g_c + ((size_t)b * NN + i) * NN;
    for (int j = t; j < NN; j += 256) {
        float xj = xs[j];
        float s = 0.f;
#pragma unroll
        for (int o = 0; o < 16; o++) {
            float h1 = fmaxf(fmaf(sw1a[o], xi, fmaf(sw1b[o], xj, sb1[o])), 0.f);
            float h2 = fmaxf(fmaf(sw1a[o], xj, fmaf(sw1b[o], xi, sb1[o])), 0.f);
            s = fmaf(sw2[o], h1 - h2, s);
        }
        crow[j] = s;
    }
}

// ---------------------------------------------------------------------------
// a0 = 1/N everywhere
// ---------------------------------------------------------------------------
__global__ void init_a0_kernel(float* __restrict__ a)
{
    size_t idx = (size_t)blockIdx.x * blockDim.x + threadIdx.x;
    a[idx] = 1.0f / (float)NN;
}

// ---------------------------------------------------------------------------
// Batched SGEMM: G[b] = c[b] (512x512) @ a[b] (512x512), fp32.
// 128x128 block tile, K-step 16, 256 threads, 8x8 per-thread microtile.
// ---------------------------------------------------------------------------
__global__ void __launch_bounds__(256) gemm_kernel(const float* __restrict__ A)
{
    const int b  = blockIdx.z;
    const int m0 = blockIdx.y * 128;
    const int n0 = blockIdx.x * 128;
    const float* Cb = g_c + (size_t)b * NN * NN;
    const float* Ab = A   + (size_t)b * NN * NN;
    float*       Gb = g_G + (size_t)b * NN * NN;

    __shared__ float Cs[16][128];   // [kk][m] (transposed on store)
    __shared__ float As[16][128];   // [kk][n]

    const int t  = threadIdx.x;
    const int tx = t & 15;          // 0..15 -> n
    const int ty = t >> 4;          // 0..15 -> m

    float acc[8][8];
#pragma unroll
    for (int u = 0; u < 8; u++)
#pragma unroll
        for (int v = 0; v < 8; v++) acc[u][v] = 0.f;

    for (int k0 = 0; k0 < NN; k0 += 16) {
        // Load C tile (128 rows x 16 cols), transpose into Cs[kk][m]
#pragma unroll
        for (int r = 0; r < 2; r++) {
            int f4  = r * 256 + t;        // 0..511 float4s
            int m   = f4 >> 2;            // 0..127
            int kk4 = (f4 & 3) * 4;       // 0,4,8,12
            float4 v = *(const float4*)(Cb + (size_t)(m0 + m) * NN + k0 + kk4);
            Cs[kk4 + 0][m] = v.x;
            Cs[kk4 + 1][m] = v.y;
            Cs[kk4 + 2][m] = v.z;
            Cs[kk4 + 3][m] = v.w;
        }
        // Load A tile (16 rows x 128 cols) directly
#pragma unroll
        for (int r = 0; r < 2; r++) {
            int f4 = r * 256 + t;
            int kk = f4 >> 5;             // 0..15
            int n4 = (f4 & 31) * 4;       // 0..124
            *(float4*)(&As[kk][n4]) =
                *(const float4*)(Ab + (size_t)(k0 + kk) * NN + n0 + n4);
        }
        __syncthreads();

#pragma unroll
        for (int kk = 0; kk < 16; kk++) {
            float rc[8], ra[8];
#pragma unroll
            for (int u = 0; u < 8; u++) rc[u] = Cs[kk][ty * 8 + u];
#pragma unroll
            for (int v = 0; v < 8; v++) ra[v] = As[kk][tx * 8 + v];
#pragma unroll
            for (int u = 0; u < 8; u++)
#pragma unroll
                for (int v = 0; v < 8; v++)
                    acc[u][v] = fmaf(rc[u], ra[v], acc[u][v]);
        }
        __syncthreads();
    }

#pragma unroll
    for (int u = 0; u < 8; u++) {
        int m = m0 + ty * 8 + u;
#pragma unroll
        for (int v4 = 0; v4 < 2; v4++) {
            float4 w = make_float4(acc[u][v4 * 4 + 0], acc[u][v4 * 4 + 1],
                                   acc[u][v4 * 4 + 2], acc[u][v4 * 4 + 3]);
            *(float4*)(Gb + (size_t)m * NN + n0 + tx * 8 + v4 * 4) = w;
        }
    }
}

// ---------------------------------------------------------------------------
// Per-row: cum = inclusive cumsum_k(G); logits = (a - lr*(G - 2*cum))/temp;
// a = softmax_k(logits). One block (512 threads) per (b,i) row, in-place.
// ---------------------------------------------------------------------------
__global__ void __launch_bounds__(512) epilogue_kernel(
    float* __restrict__ a, const float* __restrict__ lr, const int* __restrict__ temp_p)
{
    const int row  = blockIdx.x;                 // b*512 + i
    const int k    = threadIdx.x;
    const int lane = k & 31;
    const int wid  = k >> 5;

    const float* Gr = g_G + (size_t)row * NN;
    float*       ar = a   + (size_t)row * NN;

    float g  = Gr[k];
    float av = ar[k];

    // inclusive scan of g across the 512-thread block
    float v = g;
#pragma unroll
    for (int off = 1; off < 32; off <<= 1) {
        float n = __shfl_up_sync(0xffffffffu, v, off);
        if (lane >= off) v += n;
    }
    __shared__ float wsum[16];
    if (lane == 31) wsum[wid] = v;
    __syncthreads();
    if (wid == 0) {
        float w = (lane < 16) ? wsum[lane] : 0.f;
#pragma unroll
        for (int off = 1; off < 16; off <<= 1) {
            float n = __shfl_up_sync(0xffffffffu, w, off);
            if (lane >= off) w += n;
        }
        if (lane < 16) wsum[lane] = w;
    }
    __syncthreads();
    float cum = v + ((wid > 0) ? wsum[wid - 1] : 0.f);

    const float lr_abs = fabsf(lr[0]);
    const float temp   = decode_scalar(temp_p);
    float logit = (av - lr_abs * (g - 2.f * cum)) / temp;

    // block max
    __shared__ float red[16];
    float m = logit;
#pragma unroll
    for (int off = 16; off > 0; off >>= 1)
        m = fmaxf(m, __shfl_xor_sync(0xffffffffu, m, off));
    if (lane == 0) red[wid] = m;
    __syncthreads();
    if (wid == 0) {
        float mm = (lane < 16) ? red[lane] : -INFINITY;
#pragma unroll
        for (int off = 16; off > 0; off >>= 1)
            mm = fmaxf(mm, __shfl_xor_sync(0xffffffffu, mm, off));
        if (lane == 0) red[0] = mm;
    }
    __syncthreads();
    m = red[0];
    __syncthreads();   // safe to reuse red[]

    float e = expf(logit - m);
    float s = e;
#pragma unroll
    for (int off = 16; off > 0; off >>= 1)
        s += __shfl_xor_sync(0xffffffffu, s, off);
    if (lane == 0) red[wid] = s;
    __syncthreads();
    if (wid == 0) {
        float ss = (lane < 16) ? red[lane] : 0.f;
#pragma unroll
        for (int off = 16; off > 0; off >>= 1)
            ss += __shfl_xor_sync(0xffffffffu, ss, off);
        if (lane == 0) red[0] = ss;
    }
    __syncthreads();
    float total = red[0];

    ar[k] = e / total;
}

// ---------------------------------------------------------------------------
// y[b,k] = sum_i x[b,i] * a[b,i,k]
// ---------------------------------------------------------------------------
__global__ void __launch_bounds__(512) y_kernel(
    const float* __restrict__ x, const float* __restrict__ a, float* __restrict__ y)
{
    int b = blockIdx.x;
    int k = threadIdx.x;
    __shared__ float xs[NN];
    xs[k] = x[b * NN + k];
    __syncthreads();
    const float* ab = a + (size_t)b * NN * NN;
    float acc = 0.f;
    for (int i = 0; i < NN; i++)
        acc = fmaf(xs[i], ab[(size_t)i * NN + k], acc);
    y[b * NN + k] = acc;
}

// ---------------------------------------------------------------------------
extern "C" void kernel_launch(void* const* d_in, const int* in_sizes, int n_in,
                              void* d_out, int out_size)
{
    const float* x   = (const float*)d_in[0];
    const float* w1  = (const float*)d_in[1];
    const float* b1  = (const float*)d_in[2];
    const float* w2  = (const float*)d_in[3];
    // d_in[4] = b2 (cancels in c - c^T), d_in[6] = steps (fixed at 8 by setup)
    const float* lr  = (const float*)d_in[5];
    const int* temp_p = (const int*)d_in[7];

    float* y = (float*)d_out;                 // (32,1,512)
    float* a = (float*)d_out + NB * NN;       // (32,512,512), iterated in place

    compute_c_kernel<<<dim3(NN, NB), 256>>>(x, w1, b1, w2);
    init_a0_kernel<<<(NB * NN * NN) / 1024, 1024>>>(a);

    for (int s = 0; s < 8; s++) {
        gemm_kernel<<<dim3(4, 4, NB), 256>>>(a);
        epilogue_kernel<<<NB * NN, 512>>>(a, lr, temp_p);
    }

    y_kernel<<<NB, 512>>>(x, a, y);
}

// round 3
// speedup vs baseline: 2.3751x; 2.3751x over previous
#include <cuda_runtime.h>
#include <cuda_bf16.h>
#include <math.h>
#include <cstdint>

#define NB 32
#define NN 512

// Scratch (device globals; allocation-free per harness rules). 16B-aligned for
// cp.async / float4 access.
__device__ __align__(16) __nv_bfloat16 g_chh[(size_t)NB * NN * NN]; // bf16 hi of c
__device__ __align__(16) __nv_bfloat16 g_chl[(size_t)NB * NN * NN]; // bf16 lo of c
__device__ __align__(16) __nv_bfloat16 g_ath[(size_t)NB * NN * NN]; // bf16 hi of a^T
__device__ __align__(16) __nv_bfloat16 g_atl[(size_t)NB * NN * NN]; // bf16 lo of a^T
__device__ __align__(16) float         g_G[(size_t)NB * NN * NN];   // G = c @ a

// ---------------------------------------------------------------------------
__device__ __forceinline__ uint32_t smem_u32(const void* p) {
    uint32_t a;
    asm("{ .reg .u64 t; cvta.to.shared.u64 t, %1; cvt.u32.u64 %0, t; }" : "=r"(a) : "l"(p));
    return a;
}
__device__ __forceinline__ void cp_async16(uint32_t saddr, const void* gaddr) {
    asm volatile("cp.async.cg.shared.global [%0], [%1], 16;" :: "r"(saddr), "l"(gaddr) : "memory");
}
__device__ __forceinline__ void cp_commit() {
    asm volatile("cp.async.commit_group;" ::: "memory");
}
__device__ __forceinline__ void cp_wait1() {
    asm volatile("cp.async.wait_group 1;" ::: "memory");
}
__device__ __forceinline__ void cp_wait0() {
    asm volatile("cp.async.wait_group 0;" ::: "memory");
}
__device__ __forceinline__ void ldsm_x4(uint32_t* r, uint32_t addr) {
    asm volatile("ldmatrix.sync.aligned.m8n8.x4.shared.b16 {%0,%1,%2,%3}, [%4];"
                 : "=r"(r[0]), "=r"(r[1]), "=r"(r[2]), "=r"(r[3]) : "r"(addr));
}
__device__ __forceinline__ void mma_bf16(float* d, const uint32_t* a, const uint32_t* b) {
    asm volatile(
        "mma.sync.aligned.m16n8k16.row.col.f32.bf16.bf16.f32 "
        "{%0,%1,%2,%3}, {%4,%5,%6,%7}, {%8,%9}, {%0,%1,%2,%3};"
        : "+f"(d[0]), "+f"(d[1]), "+f"(d[2]), "+f"(d[3])
        : "r"(a[0]), "r"(a[1]), "r"(a[2]), "r"(a[3]), "r"(b[0]), "r"(b[1]));
}

// temp arrives as 1-elem scalar, int32 or float32 bits; decode robustly.
__device__ __forceinline__ float decode_scalar(const int* p) {
    int ib = *p;
    float f = __int_as_float(ib);
    if (isfinite(f) && fabsf(f) > 1e-30f && fabsf(f) < 1e30f) return f;
    return (float)ib;
}

// ---------------------------------------------------------------------------
// c[b,i,j] = sum_o w2[o]*(relu(w1a*xi+w1b*xj+b1) - relu(w1a*xj+w1b*xi+b1));
// store bf16 hi/lo split.
// ---------------------------------------------------------------------------
__global__ void __launch_bounds__(256) compute_c_kernel(
    const float* __restrict__ x, const float* __restrict__ w1,
    const float* __restrict__ b1, const float* __restrict__ w2)
{
    int b = blockIdx.y;
    int i = blockIdx.x;
    __shared__ float xs[NN];
    __shared__ float sw1a[16], sw1b[16], sb1[16], sw2[16];
    int t = threadIdx.x;
    if (t < 16) {
        sw1a[t] = w1[t * 2 + 0];
        sw1b[t] = w1[t * 2 + 1];
        sb1[t]  = b1[t];
        sw2[t]  = w2[t];
    }
    xs[t]       = x[b * NN + t];
    xs[t + 256] = x[b * NN + t + 256];
    __syncthreads();

    float xi = xs[i];
    size_t rowoff = ((size_t)b * NN + i) * NN;
    for (int j = t; j < NN; j += 256) {
        float xj = xs[j];
        float s = 0.f;
#pragma unroll
        for (int o = 0; o < 16; o++) {
            float h1 = fmaxf(fmaf(sw1a[o], xi, fmaf(sw1b[o], xj, sb1[o])), 0.f);
            float h2 = fmaxf(fmaf(sw1a[o], xj, fmaf(sw1b[o], xi, sb1[o])), 0.f);
            s = fmaf(sw2[o], h1 - h2, s);
        }
        __nv_bfloat16 hi = __float2bfloat16(s);
        g_chh[rowoff + j] = hi;
        g_chl[rowoff + j] = __float2bfloat16(s - __bfloat162float(hi));
    }
}

// ---------------------------------------------------------------------------
// Step 0 fused (a0 uniform): logit_k = (1/N - lr*S_i*(1-(2k+1)/N))/T  (+const),
// a = softmax_k. S_i = rowsum(c). Block(512) per row.
// ---------------------------------------------------------------------------
__global__ void __launch_bounds__(512) step0_kernel(
    float* __restrict__ a, const float* __restrict__ lr, const int* __restrict__ temp_p)
{
    const int row  = blockIdx.x;
    const int k    = threadIdx.x;
    const int lane = k & 31;
    const int wid  = k >> 5;
    size_t off = (size_t)row * NN + k;

    __shared__ float red[16];

    float v = __bfloat162float(g_chh[off]) + __bfloat162float(g_chl[off]);
#pragma unroll
    for (int o = 16; o > 0; o >>= 1) v += __shfl_xor_sync(0xffffffffu, v, o);
    if (lane == 0) red[wid] = v;
    __syncthreads();
    if (wid == 0) {
        float s = (lane < 16) ? red[lane] : 0.f;
#pragma unroll
        for (int o = 16; o > 0; o >>= 1) s += __shfl_xor_sync(0xffffffffu, s, o);
        if (lane == 0) red[0] = s;
    }
    __syncthreads();
    const float S = red[0];
    __syncthreads();

    const float lr_abs = fabsf(lr[0]);
    const float invT   = 1.f / decode_scalar(temp_p);
    const float invN   = 1.f / (float)NN;
    float logit = (invN - lr_abs * S * (1.f - (2.f * k + 1.f) * invN)) * invT;

    float m = logit;
#pragma unroll
    for (int o = 16; o > 0; o >>= 1) m = fmaxf(m, __shfl_xor_sync(0xffffffffu, m, o));
    if (lane == 0) red[wid] = m;
    __syncthreads();
    if (wid == 0) {
        float mm = (lane < 16) ? red[lane] : -INFINITY;
#pragma unroll
        for (int o = 16; o > 0; o >>= 1) mm = fmaxf(mm, __shfl_xor_sync(0xffffffffu, mm, o));
        if (lane == 0) red[0] = mm;
    }
    __syncthreads();
    m = red[0];
    __syncthreads();
    float e = __expf(logit - m);
    float s = e;
#pragma unroll
    for (int o = 16; o > 0; o >>= 1) s += __shfl_xor_sync(0xffffffffu, s, o);
    if (lane == 0) red[wid] = s;
    __syncthreads();
    if (wid == 0) {
        float ss = (lane < 16) ? red[lane] : 0.f;
#pragma unroll
        for (int o = 16; o > 0; o >>= 1) ss += __shfl_xor_sync(0xffffffffu, ss, o);
        if (lane == 0) red[0] = ss;
    }
    __syncthreads();
    a[off] = e / red[0];
}

// ---------------------------------------------------------------------------
// Transpose + bf16 split: ath[b][n][j] = bf16_hi(a[b][j][n]), atl = residual.
// ---------------------------------------------------------------------------
__global__ void __launch_bounds__(256) transpose_split_kernel(const float* __restrict__ a)
{
    __shared__ float t[32][33];
    int b  = blockIdx.z;
    int j0 = blockIdx.y * 32;
    int n0 = blockIdx.x * 32;
    int tx = threadIdx.x, ty = threadIdx.y;   // 32 x 8
    const float* ab = a + (size_t)b * NN * NN;
#pragma unroll
    for (int q = 0; q < 4; q++)
        t[ty + 8 * q][tx] = ab[(size_t)(j0 + ty + 8 * q) * NN + n0 + tx];
    __syncthreads();
    size_t boff = (size_t)b * NN * NN;
#pragma unroll
    for (int q = 0; q < 4; q++) {
        int n = n0 + ty + 8 * q;
        float v  = t[tx][ty + 8 * q];
        __nv_bfloat16 hi = __float2bfloat16(v);
        g_ath[boff + (size_t)n * NN + j0 + tx] = hi;
        g_atl[boff + (size_t)n * NN + j0 + tx] = __float2bfloat16(v - __bfloat162float(hi));
    }
}

// ---------------------------------------------------------------------------
// Batched GEMM via mma.sync bf16 (3-product split): G[b] = c[b] @ a[b].
// Block: 512 thr (16 warps, 4x4 grid of 32x32 warp tiles), tile 128x128,
// K staged in 32-chunks, cp.async double buffer, ldmatrix fragment loads.
// ---------------------------------------------------------------------------
#define PITCH 40                       // bf16 elems per smem row (bank-safe)
#define TILE_B (128 * PITCH * 2)       // 10240 bytes per matrix tile
#define STAGE_B (4 * TILE_B)           // Ahi, Alo, Bhi, Blo
#define GEMM_SMEM (2 * STAGE_B)        // 81920 bytes

__global__ void __launch_bounds__(512) gemm_mma_kernel()
{
    extern __shared__ __align__(16) char sm[];
    const int b  = blockIdx.z;
    const int m0 = blockIdx.y * 128;
    const int n0 = blockIdx.x * 128;
    const int tid  = threadIdx.x;
    const int wid  = tid >> 5;
    const int lane = tid & 31;

    const __nv_bfloat16* Ah = g_chh + (size_t)b * NN * NN;
    const __nv_bfloat16* Al = g_chl + (size_t)b * NN * NN;
    const __nv_bfloat16* Bh = g_ath + (size_t)b * NN * NN;
    const __nv_bfloat16* Bl = g_atl + (size_t)b * NN * NN;

    const uint32_t smbase = smem_u32(sm);

    // ---- stage loader: 512 threads x 4 cp.async (16B) = full 128x32 x4 tiles
    const int lrow = tid >> 2;         // 0..127
    const int lc16 = tid & 3;          // 16B chunk within 64B row
    auto load_stage = [&](int kc, int s) {
        const int k0 = kc * 32;
        const uint32_t sb = smbase + s * STAGE_B;
        const uint32_t soff = lrow * (PITCH * 2) + lc16 * 16;
        const size_t ga = (size_t)(m0 + lrow) * NN + k0 + lc16 * 8;
        const size_t gb = (size_t)(n0 + lrow) * NN + k0 + lc16 * 8;
        cp_async16(sb + 0 * TILE_B + soff, Ah + ga);
        cp_async16(sb + 1 * TILE_B + soff, Al + ga);
        cp_async16(sb + 2 * TILE_B + soff, Bh + gb);
        cp_async16(sb + 3 * TILE_B + soff, Bl + gb);
    };

    const int wm = wid & 3;            // 4 warps along M (32 rows each)
    const int wn = wid >> 2;           // 4 warps along N (32 cols each)

    float acc[2][4][4];
#pragma unroll
    for (int mi = 0; mi < 2; mi++)
#pragma unroll
        for (int ni = 0; ni < 4; ni++)
#pragma unroll
            for (int q = 0; q < 4; q++) acc[mi][ni][q] = 0.f;

    // ldmatrix lane addressing (constant per thread)
    const int a_r = (lane & 15);                     // row within 16
    const int a_c = 8 * (lane >> 4);                 // k offset 0/8
    const int b_r = (lane & 7) + ((lane & 16) >> 1); // n row within 16
    const int b_c = 8 * ((lane >> 3) & 1);           // k offset 0/8

    load_stage(0, 0);
    cp_commit();

    for (int kc = 0; kc < 16; kc++) {
        if (kc + 1 < 16) {
            load_stage(kc + 1, (kc + 1) & 1);
            cp_commit();
            cp_wait1();
        } else {
            cp_wait0();
        }
        __syncthreads();

        const uint32_t sb = smbase + (kc & 1) * STAGE_B;
#pragma unroll
        for (int ks = 0; ks < 2; ks++) {
            const int kb = ks * 16;
            uint32_t ah[2][4], al[2][4];
#pragma unroll
            for (int mi = 0; mi < 2; mi++) {
                uint32_t addr = sb + (wm * 32 + mi * 16 + a_r) * (PITCH * 2) + (kb + a_c) * 2;
                ldsm_x4(ah[mi], addr);
                ldsm_x4(al[mi], addr + TILE_B);
            }
            uint32_t bh[4][2], bl[4][2];
#pragma unroll
            for (int np = 0; np < 2; np++) {
                uint32_t addr = sb + 2 * TILE_B +
                                (wn * 32 + np * 16 + b_r) * (PITCH * 2) + (kb + b_c) * 2;
                uint32_t r[4], rl[4];
                ldsm_x4(r, addr);
                ldsm_x4(rl, addr + TILE_B);
                bh[2 * np][0] = r[0];  bh[2 * np][1] = r[1];
                bh[2 * np + 1][0] = r[2]; bh[2 * np + 1][1] = r[3];
                bl[2 * np][0] = rl[0]; bl[2 * np][1] = rl[1];
                bl[2 * np + 1][0] = rl[2]; bl[2 * np + 1][1] = rl[3];
            }
#pragma unroll
            for (int mi = 0; mi < 2; mi++)
#pragma unroll
                for (int ni = 0; ni < 4; ni++) {
                    mma_bf16(acc[mi][ni], ah[mi], bh[ni]);
                    mma_bf16(acc[mi][ni], ah[mi], bl[ni]);
                    mma_bf16(acc[mi][ni], al[mi], bh[ni]);
                }
        }
        __syncthreads();
    }

    // ---- store accumulators
    float* Gb = g_G + (size_t)b * NN * NN;
    const int g  = lane >> 2;
    const int t4 = lane & 3;
#pragma unroll
    for (int mi = 0; mi < 2; mi++) {
        int r0 = m0 + wm * 32 + mi * 16 + g;
#pragma unroll
        for (int ni = 0; ni < 4; ni++) {
            int col = n0 + wn * 32 + ni * 8 + t4 * 2;
            *(float2*)(Gb + (size_t)r0 * NN + col) =
                make_float2(acc[mi][ni][0], acc[mi][ni][1]);
            *(float2*)(Gb + (size_t)(r0 + 8) * NN + col) =
                make_float2(acc[mi][ni][2], acc[mi][ni][3]);
        }
    }
}

// ---------------------------------------------------------------------------
// Epilogue: warp per row, 16 elems/lane, shuffle-only scan/softmax.
// a <- softmax_k((a - lr*(G - 2*cumsum_k(G)))/temp)
// ---------------------------------------------------------------------------
__global__ void __launch_bounds__(256) epilogue2_kernel(
    float* __restrict__ a, const float* __restrict__ lr, const int* __restrict__ temp_p)
{
    const int row  = blockIdx.x * 8 + (threadIdx.x >> 5);
    const int lane = threadIdx.x & 31;
    const float* Gr = g_G + (size_t)row * NN;
    float*       ar = a   + (size_t)row * NN;

    float g[16], av[16];
#pragma unroll
    for (int q = 0; q < 4; q++) {
        float4 vg = *(const float4*)(Gr + lane * 16 + q * 4);
        float4 va = *(const float4*)(ar + lane * 16 + q * 4);
        g[q * 4 + 0] = vg.x; g[q * 4 + 1] = vg.y; g[q * 4 + 2] = vg.z; g[q * 4 + 3] = vg.w;
        av[q * 4 + 0] = va.x; av[q * 4 + 1] = va.y; av[q * 4 + 2] = va.z; av[q * 4 + 3] = va.w;
    }

    float p[16];
    float run = 0.f;
#pragma unroll
    for (int c = 0; c < 16; c++) { run += g[c]; p[c] = run; }
    float inc = run;
#pragma unroll
    for (int o = 1; o < 32; o <<= 1) {
        float n = __shfl_up_sync(0xffffffffu, inc, o);
        if (lane >= o) inc += n;
    }
    const float excl = inc - run;

    const float lr_abs = fabsf(lr[0]);
    const float invT   = 1.f / decode_scalar(temp_p);

    float lo[16];
    float mx = -INFINITY;
#pragma unroll
    for (int c = 0; c < 16; c++) {
        float cum = excl + p[c];
        float l = (av[c] - lr_abs * (g[c] - 2.f * cum)) * invT;
        lo[c] = l;
        mx = fmaxf(mx, l);
    }
#pragma unroll
    for (int o = 16; o > 0; o >>= 1) mx = fmaxf(mx, __shfl_xor_sync(0xffffffffu, mx, o));

    float s = 0.f;
#pragma unroll
    for (int c = 0; c < 16; c++) { lo[c] = __expf(lo[c] - mx); s += lo[c]; }
#pragma unroll
    for (int o = 16; o > 0; o >>= 1) s += __shfl_xor_sync(0xffffffffu, s, o);
    const float invS = 1.f / s;

#pragma unroll
    for (int q = 0; q < 4; q++) {
        float4 v = make_float4(lo[q * 4 + 0] * invS, lo[q * 4 + 1] * invS,
                               lo[q * 4 + 2] * invS, lo[q * 4 + 3] * invS);
        *(float4*)(ar + lane * 16 + q * 4) = v;
    }
}

// ---------------------------------------------------------------------------
// y[b,k] = sum_i x[b,i] * a[b,i,k]
// ---------------------------------------------------------------------------
__global__ void __launch_bounds__(512) y_kernel(
    const float* __restrict__ x, const float* __restrict__ a, float* __restrict__ y)
{
    int b = blockIdx.x;
    int k = threadIdx.x;
    __shared__ float xs[NN];
    xs[k] = x[b * NN + k];
    __syncthreads();
    const float* ab = a + (size_t)b * NN * NN;
    float acc = 0.f;
    for (int i = 0; i < NN; i++)
        acc = fmaf(xs[i], ab[(size_t)i * NN + k], acc);
    y[b * NN + k] = acc;
}

// ---------------------------------------------------------------------------
extern "C" void kernel_launch(void* const* d_in, const int* in_sizes, int n_in,
                              void* d_out, int out_size)
{
    const float* x   = (const float*)d_in[0];
    const float* w1  = (const float*)d_in[1];
    const float* b1  = (const float*)d_in[2];
    const float* w2  = (const float*)d_in[3];
    // d_in[4] = b2 (cancels in c - c^T), d_in[6] = steps (fixed at 8)
    const float* lr  = (const float*)d_in[5];
    const int* temp_p = (const int*)d_in[7];

    float* y = (float*)d_out;              // (32,1,512)
    float* a = (float*)d_out + NB * NN;    // (32,512,512) in-place

    cudaFuncSetAttribute(gemm_mma_kernel, cudaFuncAttributeMaxDynamicSharedMemorySize, GEMM_SMEM);

    compute_c_kernel<<<dim3(NN, NB), 256>>>(x, w1, b1, w2);
    step0_kernel<<<NB * NN, 512>>>(a, lr, temp_p);

    for (int s = 0; s < 7; s++) {
        transpose_split_kernel<<<dim3(16, 16, NB), dim3(32, 8)>>>(a);
        gemm_mma_kernel<<<dim3(4, 4, NB), 512, GEMM_SMEM>>>();
        epilogue2_kernel<<<NB * NN / 8, 256>>>(a, lr, temp_p);
    }

    y_kernel<<<NB, 512>>>(x, a, y);
}

// round 4
// speedup vs baseline: 2.8820x; 1.2134x over previous
#include <cuda_runtime.h>
#include <cuda_bf16.h>
#include <math.h>
#include <cstdint>

#define NB 32
#define NN 512

// Scratch (device globals; allocation-free per harness rules).
__device__ __align__(16) __nv_bfloat16 g_chh[(size_t)NB * NN * NN]; // bf16 hi of c [m][k]
__device__ __align__(16) __nv_bfloat16 g_chl[(size_t)NB * NN * NN]; // bf16 lo of c
__device__ __align__(16) __nv_bfloat16 g_ahh[(size_t)NB * NN * NN]; // bf16 hi of a [j][n] (row-major!)
__device__ __align__(16) __nv_bfloat16 g_ahl[(size_t)NB * NN * NN]; // bf16 lo of a
__device__ __align__(16) float         g_G[(size_t)NB * NN * NN];   // G = c @ a

// ---------------------------------------------------------------------------
__device__ __forceinline__ uint32_t smem_u32(const void* p) {
    uint32_t a;
    asm("{ .reg .u64 t; cvta.to.shared.u64 t, %1; cvt.u32.u64 %0, t; }" : "=r"(a) : "l"(p));
    return a;
}
__device__ __forceinline__ void cp_async16(uint32_t saddr, const void* gaddr) {
    asm volatile("cp.async.cg.shared.global [%0], [%1], 16;" :: "r"(saddr), "l"(gaddr) : "memory");
}
__device__ __forceinline__ void cp_commit() { asm volatile("cp.async.commit_group;" ::: "memory"); }
__device__ __forceinline__ void cp_wait1()  { asm volatile("cp.async.wait_group 1;" ::: "memory"); }
__device__ __forceinline__ void cp_wait0()  { asm volatile("cp.async.wait_group 0;" ::: "memory"); }
__device__ __forceinline__ void ldsm_x4(uint32_t* r, uint32_t addr) {
    asm volatile("ldmatrix.sync.aligned.m8n8.x4.shared.b16 {%0,%1,%2,%3}, [%4];"
                 : "=r"(r[0]), "=r"(r[1]), "=r"(r[2]), "=r"(r[3]) : "r"(addr));
}
__device__ __forceinline__ void ldsm_x4_t(uint32_t* r, uint32_t addr) {
    asm volatile("ldmatrix.sync.aligned.m8n8.x4.trans.shared.b16 {%0,%1,%2,%3}, [%4];"
                 : "=r"(r[0]), "=r"(r[1]), "=r"(r[2]), "=r"(r[3]) : "r"(addr));
}
__device__ __forceinline__ void mma_bf16(float* d, const uint32_t* a, const uint32_t* b) {
    asm volatile(
        "mma.sync.aligned.m16n8k16.row.col.f32.bf16.bf16.f32 "
        "{%0,%1,%2,%3}, {%4,%5,%6,%7}, {%8,%9}, {%0,%1,%2,%3};"
        : "+f"(d[0]), "+f"(d[1]), "+f"(d[2]), "+f"(d[3])
        : "r"(a[0]), "r"(a[1]), "r"(a[2]), "r"(a[3]), "r"(b[0]), "r"(b[1]));
}

// temp arrives as 1-elem scalar, int32 or float32 bits; decode robustly.
__device__ __forceinline__ float decode_scalar(const int* p) {
    int ib = *p;
    float f = __int_as_float(ib);
    if (isfinite(f) && fabsf(f) > 1e-30f && fabsf(f) < 1e30f) return f;
    return (float)ib;
}

// ---------------------------------------------------------------------------
// c[b,i,j] = sum_o w2[o]*(relu(w1a*xi+w1b*xj+b1) - relu(w1a*xj+w1b*xi+b1));
// store bf16 hi/lo split (K-contiguous [m][k]).
// ---------------------------------------------------------------------------
__global__ void __launch_bounds__(256) compute_c_kernel(
    const float* __restrict__ x, const float* __restrict__ w1,
    const float* __restrict__ b1, const float* __restrict__ w2)
{
    int b = blockIdx.y;
    int i = blockIdx.x;
    __shared__ float xs[NN];
    __shared__ float sw1a[16], sw1b[16], sb1[16], sw2[16];
    int t = threadIdx.x;
    if (t < 16) {
        sw1a[t] = w1[t * 2 + 0];
        sw1b[t] = w1[t * 2 + 1];
        sb1[t]  = b1[t];
        sw2[t]  = w2[t];
    }
    xs[t]       = x[b * NN + t];
    xs[t + 256] = x[b * NN + t + 256];
    __syncthreads();

    float xi = xs[i];
    size_t rowoff = ((size_t)b * NN + i) * NN;
    for (int j = t; j < NN; j += 256) {
        float xj = xs[j];
        float s = 0.f;
#pragma unroll
        for (int o = 0; o < 16; o++) {
            float h1 = fmaxf(fmaf(sw1a[o], xi, fmaf(sw1b[o], xj, sb1[o])), 0.f);
            float h2 = fmaxf(fmaf(sw1a[o], xj, fmaf(sw1b[o], xi, sb1[o])), 0.f);
            s = fmaf(sw2[o], h1 - h2, s);
        }
        __nv_bfloat16 hi = __float2bfloat16(s);
        g_chh[rowoff + j] = hi;
        g_chl[rowoff + j] = __float2bfloat16(s - __bfloat162float(hi));
    }
}

// ---------------------------------------------------------------------------
// Step 0 fused (a0 uniform). Writes a as bf16 hi/lo (row-major).
// ---------------------------------------------------------------------------
__global__ void __launch_bounds__(512) step0_kernel(
    const float* __restrict__ lr, const int* __restrict__ temp_p)
{
    const int row  = blockIdx.x;
    const int k    = threadIdx.x;
    const int lane = k & 31;
    const int wid  = k >> 5;
    size_t off = (size_t)row * NN + k;

    __shared__ float red[16];

    float v = __bfloat162float(g_chh[off]) + __bfloat162float(g_chl[off]);
#pragma unroll
    for (int o = 16; o > 0; o >>= 1) v += __shfl_xor_sync(0xffffffffu, v, o);
    if (lane == 0) red[wid] = v;
    __syncthreads();
    if (wid == 0) {
        float s = (lane < 16) ? red[lane] : 0.f;
#pragma unroll
        for (int o = 16; o > 0; o >>= 1) s += __shfl_xor_sync(0xffffffffu, s, o);
        if (lane == 0) red[0] = s;
    }
    __syncthreads();
    const float S = red[0];
    __syncthreads();

    const float lr_abs = fabsf(lr[0]);
    const float invT   = 1.f / decode_scalar(temp_p);
    const float invN   = 1.f / (float)NN;
    float logit = (invN - lr_abs * S * (1.f - (2.f * k + 1.f) * invN)) * invT;

    float m = logit;
#pragma unroll
    for (int o = 16; o > 0; o >>= 1) m = fmaxf(m, __shfl_xor_sync(0xffffffffu, m, o));
    if (lane == 0) red[wid] = m;
    __syncthreads();
    if (wid == 0) {
        float mm = (lane < 16) ? red[lane] : -INFINITY;
#pragma unroll
        for (int o = 16; o > 0; o >>= 1) mm = fmaxf(mm, __shfl_xor_sync(0xffffffffu, mm, o));
        if (lane == 0) red[0] = mm;
    }
    __syncthreads();
    m = red[0];
    __syncthreads();
    float e = __expf(logit - m);
    float s = e;
#pragma unroll
    for (int o = 16; o > 0; o >>= 1) s += __shfl_xor_sync(0xffffffffu, s, o);
    if (lane == 0) red[wid] = s;
    __syncthreads();
    if (wid == 0) {
        float ss = (lane < 16) ? red[lane] : 0.f;
#pragma unroll
        for (int o = 16; o > 0; o >>= 1) ss += __shfl_xor_sync(0xffffffffu, ss, o);
        if (lane == 0) red[0] = ss;
    }
    __syncthreads();
    float av = e / red[0];
    __nv_bfloat16 hi = __float2bfloat16(av);
    g_ahh[off] = hi;
    g_ahl[off] = __float2bfloat16(av - __bfloat162float(hi));
}

// ---------------------------------------------------------------------------
// Batched GEMM: G[b] = c[b] @ a[b] via mma.sync bf16 3-product split.
// 256 thr (8 warps: 4M x 2N, warp tile 32x64), block tile 128x128,
// K chunks of 32, cp.async double buffer. B loaded from row-major a hi/lo
// ([k][n]) via ldmatrix.trans -> no transpose kernel needed.
// ---------------------------------------------------------------------------
#define PA 40                          // A smem pitch (bf16), 80B rows
#define PB 136                         // B smem pitch (bf16), 272B rows (17x16B)
#define A_TILE_B (128 * PA * 2)        // 10240 B per split
#define B_TILE_B (32 * PB * 2)         // 8704 B per split
#define STAGE_B (2 * A_TILE_B + 2 * B_TILE_B)   // 37888
#define GEMM_SMEM (2 * STAGE_B)        // 75776

__global__ void __launch_bounds__(256, 2) gemm_mma_kernel()
{
    extern __shared__ __align__(16) char sm[];
    const int b  = blockIdx.z;
    const int m0 = blockIdx.y * 128;
    const int n0 = blockIdx.x * 128;
    const int tid  = threadIdx.x;
    const int wid  = tid >> 5;
    const int lane = tid & 31;

    const __nv_bfloat16* Ah = g_chh + (size_t)b * NN * NN;
    const __nv_bfloat16* Al = g_chl + (size_t)b * NN * NN;
    const __nv_bfloat16* Bh = g_ahh + (size_t)b * NN * NN;
    const __nv_bfloat16* Bl = g_ahl + (size_t)b * NN * NN;

    const uint32_t smbase = smem_u32(sm);

    auto load_stage = [&](int kc, int s) {
        const int k0 = kc * 32;
        const uint32_t sb = smbase + s * STAGE_B;
        // A tiles: 128 rows x 32k, 4 16B-chunks/row, 2 splits
#pragma unroll
        for (int it = 0; it < 2; it++) {
            int idx = it * 256 + tid;          // 0..511
            int r   = idx >> 2;                // 0..127
            int c   = idx & 3;                 // 0..3
            uint32_t so = (uint32_t)(r * (PA * 2) + c * 16);
            size_t ga = (size_t)(m0 + r) * NN + k0 + c * 8;
            cp_async16(sb + so, Ah + ga);
            cp_async16(sb + A_TILE_B + so, Al + ga);
        }
        // B tiles: 32 k-rows x 128n, 16 16B-chunks/row, 2 splits
#pragma unroll
        for (int it = 0; it < 2; it++) {
            int idx = it * 256 + tid;          // 0..511
            int r   = idx >> 4;                // 0..31
            int c   = idx & 15;                // 0..15
            uint32_t so = (uint32_t)(r * (PB * 2) + c * 16);
            size_t gb = (size_t)(k0 + r) * NN + n0 + c * 8;
            cp_async16(sb + 2 * A_TILE_B + so, Bh + gb);
            cp_async16(sb + 2 * A_TILE_B + B_TILE_B + so, Bl + gb);
        }
    };

    const int wm = wid & 3;            // M quadrant (32 rows)
    const int wn = wid >> 2;           // N half (64 cols)

    float acc[2][8][4];
#pragma unroll
    for (int mi = 0; mi < 2; mi++)
#pragma unroll
        for (int ni = 0; ni < 8; ni++)
#pragma unroll
            for (int q = 0; q < 4; q++) acc[mi][ni][q] = 0.f;

    const int l_r = lane & 15;         // row within 16 (A rows / B k-rows)
    const int l_c = 8 * (lane >> 4);   // 8-offset (A k / B n)

    load_stage(0, 0);
    cp_commit();

    for (int kc = 0; kc < 16; kc++) {
        if (kc + 1 < 16) {
            load_stage(kc + 1, (kc + 1) & 1);
            cp_commit();
            cp_wait1();
        } else {
            cp_wait0();
        }
        __syncthreads();

        const uint32_t sb = smbase + (kc & 1) * STAGE_B;
#pragma unroll
        for (int ks = 0; ks < 2; ks++) {
            const int kb = ks * 16;
            uint32_t ah[2][4], al[2][4];
#pragma unroll
            for (int mi = 0; mi < 2; mi++) {
                uint32_t addr = sb + (wm * 32 + mi * 16 + l_r) * (PA * 2) + (kb + l_c) * 2;
                ldsm_x4(ah[mi], addr);
                ldsm_x4(al[mi], addr + A_TILE_B);
            }
#pragma unroll
            for (int nh = 0; nh < 2; nh++) {
                uint32_t bh[4][2], bl[4][2];
                const int nbase = wn * 64 + nh * 32;
#pragma unroll
                for (int t16 = 0; t16 < 2; t16++) {
                    uint32_t addr = sb + 2 * A_TILE_B +
                                    (kb + l_r) * (PB * 2) + (nbase + t16 * 16 + l_c) * 2;
                    uint32_t r4[4], rl4[4];
                    ldsm_x4_t(r4, addr);
                    ldsm_x4_t(rl4, addr + B_TILE_B);
                    bh[t16 * 2][0] = r4[0];      bh[t16 * 2][1] = r4[1];
                    bh[t16 * 2 + 1][0] = r4[2];  bh[t16 * 2 + 1][1] = r4[3];
                    bl[t16 * 2][0] = rl4[0];     bl[t16 * 2][1] = rl4[1];
                    bl[t16 * 2 + 1][0] = rl4[2]; bl[t16 * 2 + 1][1] = rl4[3];
                }
#pragma unroll
                for (int mi = 0; mi < 2; mi++)
#pragma unroll
                    for (int ni4 = 0; ni4 < 4; ni4++) {
                        float* a4 = acc[mi][nh * 4 + ni4];
                        mma_bf16(a4, ah[mi], bh[ni4]);
                        mma_bf16(a4, ah[mi], bl[ni4]);
                        mma_bf16(a4, al[mi], bh[ni4]);
                    }
            }
        }
        __syncthreads();
    }

    float* Gb = g_G + (size_t)b * NN * NN;
    const int g  = lane >> 2;
    const int t4 = lane & 3;
#pragma unroll
    for (int mi = 0; mi < 2; mi++) {
        int r0 = m0 + wm * 32 + mi * 16 + g;
#pragma unroll
        for (int ni = 0; ni < 8; ni++) {
            int col = n0 + wn * 64 + ni * 8 + t4 * 2;
            *(float2*)(Gb + (size_t)r0 * NN + col) =
                make_float2(acc[mi][ni][0], acc[mi][ni][1]);
            *(float2*)(Gb + (size_t)(r0 + 8) * NN + col) =
                make_float2(acc[mi][ni][2], acc[mi][ni][3]);
        }
    }
}

// ---------------------------------------------------------------------------
// Epilogue fused: warp per row. Reads G + a(hi/lo), computes
// a' = softmax_k((a - lr*(G - 2*cumsum_k(G)))/temp); writes a' hi/lo.
// On the last step also writes fp32 a' (the output).
// ---------------------------------------------------------------------------
__global__ void __launch_bounds__(256) epi_fuse_kernel(
    float* __restrict__ a_out, const float* __restrict__ lr,
    const int* __restrict__ temp_p, int last)
{
    const int row  = blockIdx.x * 8 + (threadIdx.x >> 5);
    const int lane = threadIdx.x & 31;
    const size_t base = (size_t)row * NN + lane * 16;
    const float* Gr = g_G + base;

    float g[16];
#pragma unroll
    for (int q = 0; q < 4; q++) {
        float4 vg = *(const float4*)(Gr + q * 4);
        g[q * 4 + 0] = vg.x; g[q * 4 + 1] = vg.y; g[q * 4 + 2] = vg.z; g[q * 4 + 3] = vg.w;
    }

    union U16 { uint4 u4[2]; __nv_bfloat16 h[16]; };
    U16 uh, ul;
    uh.u4[0] = *(const uint4*)(g_ahh + base);
    uh.u4[1] = *(const uint4*)(g_ahh + base + 8);
    ul.u4[0] = *(const uint4*)(g_ahl + base);
    ul.u4[1] = *(const uint4*)(g_ahl + base + 8);

    float av[16];
#pragma unroll
    for (int c = 0; c < 16; c++)
        av[c] = __bfloat162float(uh.h[c]) + __bfloat162float(ul.h[c]);

    float p[16];
    float run = 0.f;
#pragma unroll
    for (int c = 0; c < 16; c++) { run += g[c]; p[c] = run; }
    float inc = run;
#pragma unroll
    for (int o = 1; o < 32; o <<= 1) {
        float n = __shfl_up_sync(0xffffffffu, inc, o);
        if (lane >= o) inc += n;
    }
    const float excl = inc - run;

    const float lr_abs = fabsf(lr[0]);
    const float invT   = 1.f / decode_scalar(temp_p);

    float lo[16];
    float mx = -INFINITY;
#pragma unroll
    for (int c = 0; c < 16; c++) {
        float cum = excl + p[c];
        float l = (av[c] - lr_abs * (g[c] - 2.f * cum)) * invT;
        lo[c] = l;
        mx = fmaxf(mx, l);
    }
#pragma unroll
    for (int o = 16; o > 0; o >>= 1) mx = fmaxf(mx, __shfl_xor_sync(0xffffffffu, mx, o));

    float s = 0.f;
#pragma unroll
    for (int c = 0; c < 16; c++) { lo[c] = __expf(lo[c] - mx); s += lo[c]; }
#pragma unroll
    for (int o = 16; o > 0; o >>= 1) s += __shfl_xor_sync(0xffffffffu, s, o);
    const float invS = 1.f / s;

    U16 oh, ol;
#pragma unroll
    for (int c = 0; c < 16; c++) {
        float v = lo[c] * invS;
        __nv_bfloat16 hi = __float2bfloat16(v);
        oh.h[c] = hi;
        ol.h[c] = __float2bfloat16(v - __bfloat162float(hi));
        lo[c] = v;
    }
    *(uint4*)(g_ahh + base)     = oh.u4[0];
    *(uint4*)(g_ahh + base + 8) = oh.u4[1];
    *(uint4*)(g_ahl + base)     = ol.u4[0];
    *(uint4*)(g_ahl + base + 8) = ol.u4[1];

    if (last) {
        float* ar = a_out + base;
#pragma unroll
        for (int q = 0; q < 4; q++)
            *(float4*)(ar + q * 4) = make_float4(lo[q * 4 + 0], lo[q * 4 + 1],
                                                 lo[q * 4 + 2], lo[q * 4 + 3]);
    }
}

// ---------------------------------------------------------------------------
// y[b,k] = sum_i x[b,i] * a[b,i,k]; 4 i-chunks per batch + atomicAdd.
// ---------------------------------------------------------------------------
__global__ void init_y_kernel(float* __restrict__ y)
{
    y[blockIdx.x * 1024 + threadIdx.x] = 0.f;
}

__global__ void __launch_bounds__(512) y_kernel(
    const float* __restrict__ x, const float* __restrict__ a, float* __restrict__ y)
{
    int b  = blockIdx.x;
    int ch = blockIdx.y;
    int k  = threadIdx.x;
    __shared__ float xs[128];
    if (k < 128) xs[k] = x[b * NN + ch * 128 + k];
    __syncthreads();
    const float* ab = a + (size_t)b * NN * NN + (size_t)ch * 128 * NN;
    float a0 = 0.f, a1 = 0.f, a2 = 0.f, a3 = 0.f;
#pragma unroll 4
    for (int i = 0; i < 128; i += 4) {
        a0 = fmaf(xs[i + 0], ab[(size_t)(i + 0) * NN + k], a0);
        a1 = fmaf(xs[i + 1], ab[(size_t)(i + 1) * NN + k], a1);
        a2 = fmaf(xs[i + 2], ab[(size_t)(i + 2) * NN + k], a2);
        a3 = fmaf(xs[i + 3], ab[(size_t)(i + 3) * NN + k], a3);
    }
    atomicAdd(&y[b * NN + k], (a0 + a1) + (a2 + a3));
}

// ---------------------------------------------------------------------------
extern "C" void kernel_launch(void* const* d_in, const int* in_sizes, int n_in,
                              void* d_out, int out_size)
{
    const float* x   = (const float*)d_in[0];
    const float* w1  = (const float*)d_in[1];
    const float* b1  = (const float*)d_in[2];
    const float* w2  = (const float*)d_in[3];
    // d_in[4] = b2 (cancels in c - c^T), d_in[6] = steps (fixed at 8)
    const float* lr  = (const float*)d_in[5];
    const int* temp_p = (const int*)d_in[7];

    float* y = (float*)d_out;              // (32,1,512)
    float* a = (float*)d_out + NB * NN;    // (32,512,512), written on last step

    cudaFuncSetAttribute(gemm_mma_kernel, cudaFuncAttributeMaxDynamicSharedMemorySize, GEMM_SMEM);

    compute_c_kernel<<<dim3(NN, NB), 256>>>(x, w1, b1, w2);
    step0_kernel<<<NB * NN, 512>>>(lr, temp_p);

    for (int s = 0; s < 7; s++) {
        gemm_mma_kernel<<<dim3(4, 4, NB), 256, GEMM_SMEM>>>();
        epi_fuse_kernel<<<NB * NN / 8, 256>>>(a, lr, temp_p, (s == 6) ? 1 : 0);
    }

    init_y_kernel<<<NB * NN / 1024, 1024>>>(y);
    y_kernel<<<dim3(NB, 4), 512>>>(x, a, y);
}

// round 5
// speedup vs baseline: 2.9886x; 1.0370x over previous
#include <cuda_runtime.h>
#include <cuda_bf16.h>
#include <math.h>
#include <cstdint>

#define NB 32
#define NN 512

// Scratch (device globals; allocation-free per harness rules).
__device__ __align__(16) __nv_bfloat16 g_chh[(size_t)NB * NN * NN]; // bf16 hi of c [m][k]
__device__ __align__(16) __nv_bfloat16 g_chl[(size_t)NB * NN * NN]; // bf16 lo of c
__device__ __align__(16) __nv_bfloat16 g_ahh[(size_t)NB * NN * NN]; // bf16 hi of a [j][n] row-major
__device__ __align__(16) __nv_bfloat16 g_ahl[(size_t)NB * NN * NN]; // bf16 lo of a
__device__ __align__(16) float         g_G[(size_t)NB * NN * NN];   // G = c @ a

// ---------------------------------------------------------------------------
__device__ __forceinline__ uint32_t smem_u32(const void* p) {
    uint32_t a;
    asm("{ .reg .u64 t; cvta.to.shared.u64 t, %1; cvt.u32.u64 %0, t; }" : "=r"(a) : "l"(p));
    return a;
}
__device__ __forceinline__ void cp_async16(uint32_t saddr, const void* gaddr) {
    asm volatile("cp.async.cg.shared.global [%0], [%1], 16;" :: "r"(saddr), "l"(gaddr) : "memory");
}
__device__ __forceinline__ void cp_commit() { asm volatile("cp.async.commit_group;" ::: "memory"); }
__device__ __forceinline__ void cp_wait3()  { asm volatile("cp.async.wait_group 3;" ::: "memory"); }
__device__ __forceinline__ void cp_wait0()  { asm volatile("cp.async.wait_group 0;" ::: "memory"); }
__device__ __forceinline__ void ldsm_x4(uint32_t* r, uint32_t addr) {
    asm volatile("ldmatrix.sync.aligned.m8n8.x4.shared.b16 {%0,%1,%2,%3}, [%4];"
                 : "=r"(r[0]), "=r"(r[1]), "=r"(r[2]), "=r"(r[3]) : "r"(addr));
}
__device__ __forceinline__ void ldsm_x4_t(uint32_t* r, uint32_t addr) {
    asm volatile("ldmatrix.sync.aligned.m8n8.x4.trans.shared.b16 {%0,%1,%2,%3}, [%4];"
                 : "=r"(r[0]), "=r"(r[1]), "=r"(r[2]), "=r"(r[3]) : "r"(addr));
}
__device__ __forceinline__ void mma_bf16(float* d, const uint32_t* a, const uint32_t* b) {
    asm volatile(
        "mma.sync.aligned.m16n8k16.row.col.f32.bf16.bf16.f32 "
        "{%0,%1,%2,%3}, {%4,%5,%6,%7}, {%8,%9}, {%0,%1,%2,%3};"
        : "+f"(d[0]), "+f"(d[1]), "+f"(d[2]), "+f"(d[3])
        : "r"(a[0]), "r"(a[1]), "r"(a[2]), "r"(a[3]), "r"(b[0]), "r"(b[1]));
}

// temp arrives as 1-elem scalar, int32 or float32 bits; decode robustly.
__device__ __forceinline__ float decode_scalar(const int* p) {
    int ib = *p;
    float f = __int_as_float(ib);
    if (isfinite(f) && fabsf(f) > 1e-30f && fabsf(f) < 1e30f) return f;
    return (float)ib;
}

// ---------------------------------------------------------------------------
// c[b,i,j]: 8 rows per block, 256 threads.
// ---------------------------------------------------------------------------
__global__ void __launch_bounds__(256) compute_c_kernel(
    const float* __restrict__ x, const float* __restrict__ w1,
    const float* __restrict__ b1, const float* __restrict__ w2)
{
    int b  = blockIdx.y;
    int i0 = blockIdx.x * 8;
    __shared__ float xs[NN];
    __shared__ float sw1a[16], sw1b[16], sb1[16], sw2[16];
    int t = threadIdx.x;
    if (t < 16) {
        sw1a[t] = w1[t * 2 + 0];
        sw1b[t] = w1[t * 2 + 1];
        sb1[t]  = b1[t];
        sw2[t]  = w2[t];
    }
    xs[t]       = x[b * NN + t];
    xs[t + 256] = x[b * NN + t + 256];
    __syncthreads();

    for (int ii = 0; ii < 8; ii++) {
        int i = i0 + ii;
        float xi = xs[i];
        size_t rowoff = ((size_t)b * NN + i) * NN;
        for (int j = t; j < NN; j += 256) {
            float xj = xs[j];
            float s = 0.f;
#pragma unroll
            for (int o = 0; o < 16; o++) {
                float h1 = fmaxf(fmaf(sw1a[o], xi, fmaf(sw1b[o], xj, sb1[o])), 0.f);
                float h2 = fmaxf(fmaf(sw1a[o], xj, fmaf(sw1b[o], xi, sb1[o])), 0.f);
                s = fmaf(sw2[o], h1 - h2, s);
            }
            __nv_bfloat16 hi = __float2bfloat16(s);
            g_chh[rowoff + j] = hi;
            g_chl[rowoff + j] = __float2bfloat16(s - __bfloat162float(hi));
        }
    }
}

// ---------------------------------------------------------------------------
// Step 0 fused (a0 uniform). Writes a as bf16 hi/lo (row-major).
// ---------------------------------------------------------------------------
__global__ void __launch_bounds__(512) step0_kernel(
    const float* __restrict__ lr, const int* __restrict__ temp_p)
{
    const int row  = blockIdx.x;
    const int k    = threadIdx.x;
    const int lane = k & 31;
    const int wid  = k >> 5;
    size_t off = (size_t)row * NN + k;

    __shared__ float red[16];

    float v = __bfloat162float(g_chh[off]) + __bfloat162float(g_chl[off]);
#pragma unroll
    for (int o = 16; o > 0; o >>= 1) v += __shfl_xor_sync(0xffffffffu, v, o);
    if (lane == 0) red[wid] = v;
    __syncthreads();
    if (wid == 0) {
        float s = (lane < 16) ? red[lane] : 0.f;
#pragma unroll
        for (int o = 16; o > 0; o >>= 1) s += __shfl_xor_sync(0xffffffffu, s, o);
        if (lane == 0) red[0] = s;
    }
    __syncthreads();
    const float S = red[0];
    __syncthreads();

    const float lr_abs = fabsf(lr[0]);
    const float invT   = 1.f / decode_scalar(temp_p);
    const float invN   = 1.f / (float)NN;
    float logit = (invN - lr_abs * S * (1.f - (2.f * k + 1.f) * invN)) * invT;

    float m = logit;
#pragma unroll
    for (int o = 16; o > 0; o >>= 1) m = fmaxf(m, __shfl_xor_sync(0xffffffffu, m, o));
    if (lane == 0) red[wid] = m;
    __syncthreads();
    if (wid == 0) {
        float mm = (lane < 16) ? red[lane] : -INFINITY;
#pragma unroll
        for (int o = 16; o > 0; o >>= 1) mm = fmaxf(mm, __shfl_xor_sync(0xffffffffu, mm, o));
        if (lane == 0) red[0] = mm;
    }
    __syncthreads();
    m = red[0];
    __syncthreads();
    float e = __expf(logit - m);
    float s = e;
#pragma unroll
    for (int o = 16; o > 0; o >>= 1) s += __shfl_xor_sync(0xffffffffu, s, o);
    if (lane == 0) red[wid] = s;
    __syncthreads();
    if (wid == 0) {
        float ss = (lane < 16) ? red[lane] : 0.f;
#pragma unroll
        for (int o = 16; o > 0; o >>= 1) ss += __shfl_xor_sync(0xffffffffu, ss, o);
        if (lane == 0) red[0] = ss;
    }
    __syncthreads();
    float av = e / red[0];
    __nv_bfloat16 hi = __float2bfloat16(av);
    g_ahh[off] = hi;
    g_ahl[off] = __float2bfloat16(av - __bfloat162float(hi));
}

// ---------------------------------------------------------------------------
// Batched GEMM: G[b] = c[b] @ a[b], mma.sync bf16 3-product split.
// 256 thr (8 warps: 4M x 2N, warp tile 32x64), block tile 128x128.
// 5-stage cp.async ring, K=16 per stage, prefetch distance 4, one sync/stage.
// ---------------------------------------------------------------------------
#define PA 24                          // A smem pitch in bf16 (48 B rows: conflict-free)
#define PB 136                         // B smem pitch in bf16 (272 B rows)
#define A_TILE_B (128 * PA * 2)        // 6144 B per split
#define B_TILE_B (16 * PB * 2)         // 4352 B per split
#define STAGE_B  (2 * A_TILE_B + 2 * B_TILE_B)   // 20992
#define NSTAGE 5
#define GEMM_SMEM (NSTAGE * STAGE_B)   // 104960

__global__ void __launch_bounds__(256, 2) gemm_mma_kernel()
{
    extern __shared__ __align__(16) char sm[];
    const int b  = blockIdx.z;
    const int m0 = blockIdx.y * 128;
    const int n0 = blockIdx.x * 128;
    const int tid  = threadIdx.x;
    const int wid  = tid >> 5;
    const int lane = tid & 31;

    const __nv_bfloat16* Ah = g_chh + (size_t)b * NN * NN;
    const __nv_bfloat16* Al = g_chl + (size_t)b * NN * NN;
    const __nv_bfloat16* Bh = g_ahh + (size_t)b * NN * NN;
    const __nv_bfloat16* Bl = g_ahl + (size_t)b * NN * NN;

    const uint32_t smbase = smem_u32(sm);

    // per-stage: A 128r x 16k (2 x 16B chunks/row) x2 splits = 512 cp;
    //            B 16k x 128n (16 x 16B chunks/row) x2 splits = 512 cp;
    //            1024 cp / 256 thr = 4 per thread.
    const int ar = tid >> 1;           // 0..127 A row
    const int ac = tid & 1;            // 16B chunk
    const int br = tid >> 4;           // 0..15 B k-row
    const int bc = tid & 15;           // 16B chunk
    auto load_stage = [&](int ks16) {
        const int k0 = ks16 * 16;
        const uint32_t sb = smbase + (ks16 % NSTAGE) * STAGE_B;
        uint32_t sa = sb + (uint32_t)(ar * (PA * 2) + ac * 16);
        size_t ga = (size_t)(m0 + ar) * NN + k0 + ac * 8;
        cp_async16(sa, Ah + ga);
        cp_async16(sa + A_TILE_B, Al + ga);
        uint32_t sB = sb + 2 * A_TILE_B + (uint32_t)(br * (PB * 2) + bc * 16);
        size_t gb = (size_t)(k0 + br) * NN + n0 + bc * 8;
        cp_async16(sB, Bh + gb);
        cp_async16(sB + B_TILE_B, Bl + gb);
        cp_commit();
    };

    const int wm = wid & 3;            // M quadrant (32 rows)
    const int wn = wid >> 2;           // N half (64 cols)

    float acc[2][8][4];
#pragma unroll
    for (int mi = 0; mi < 2; mi++)
#pragma unroll
        for (int ni = 0; ni < 8; ni++)
#pragma unroll
            for (int q = 0; q < 4; q++) acc[mi][ni][q] = 0.f;

    const int l_r = lane & 15;
    const int l_c = 8 * (lane >> 4);

#pragma unroll
    for (int s = 0; s < NSTAGE - 1; s++) load_stage(s);

    for (int s = 0; s < 32; s++) {
        cp_wait3();
        __syncthreads();

        const uint32_t sb = smbase + (s % NSTAGE) * STAGE_B;
        uint32_t ah[2][4], al[2][4];
#pragma unroll
        for (int mi = 0; mi < 2; mi++) {
            uint32_t addr = sb + (wm * 32 + mi * 16 + l_r) * (PA * 2) + l_c * 2;
            ldsm_x4(ah[mi], addr);
            ldsm_x4(al[mi], addr + A_TILE_B);
        }
#pragma unroll
        for (int nh = 0; nh < 2; nh++) {
            uint32_t bh[4][2], bl[4][2];
            const int nbase = wn * 64 + nh * 32;
#pragma unroll
            for (int t16 = 0; t16 < 2; t16++) {
                uint32_t addr = sb + 2 * A_TILE_B +
                                l_r * (PB * 2) + (nbase + t16 * 16 + l_c) * 2;
                uint32_t r4[4], rl4[4];
                ldsm_x4_t(r4, addr);
                ldsm_x4_t(rl4, addr + B_TILE_B);
                bh[t16 * 2][0] = r4[0];      bh[t16 * 2][1] = r4[1];
                bh[t16 * 2 + 1][0] = r4[2];  bh[t16 * 2 + 1][1] = r4[3];
                bl[t16 * 2][0] = rl4[0];     bl[t16 * 2][1] = rl4[1];
                bl[t16 * 2 + 1][0] = rl4[2]; bl[t16 * 2 + 1][1] = rl4[3];
            }
#pragma unroll
            for (int mi = 0; mi < 2; mi++)
#pragma unroll
                for (int ni4 = 0; ni4 < 4; ni4++) {
                    float* a4 = acc[mi][nh * 4 + ni4];
                    mma_bf16(a4, ah[mi], bh[ni4]);
                    mma_bf16(a4, ah[mi], bl[ni4]);
                    mma_bf16(a4, al[mi], bh[ni4]);
                }
        }

        if (s + NSTAGE - 1 < 32) load_stage(s + NSTAGE - 1);
    }
    cp_wait0();

    float* Gb = g_G + (size_t)b * NN * NN;
    const int g  = lane >> 2;
    const int t4 = lane & 3;
#pragma unroll
    for (int mi = 0; mi < 2; mi++) {
        int r0 = m0 + wm * 32 + mi * 16 + g;
#pragma unroll
        for (int ni = 0; ni < 8; ni++) {
            int col = n0 + wn * 64 + ni * 8 + t4 * 2;
            *(float2*)(Gb + (size_t)r0 * NN + col) =
                make_float2(acc[mi][ni][0], acc[mi][ni][1]);
            *(float2*)(Gb + (size_t)(r0 + 8) * NN + col) =
                make_float2(acc[mi][ni][2], acc[mi][ni][3]);
        }
    }
}

// ---------------------------------------------------------------------------
// Epilogue fused: warp per row; reads G + a(hi/lo); writes a' hi/lo
// (+ fp32 a' on last step).
// ---------------------------------------------------------------------------
__global__ void __launch_bounds__(256) epi_fuse_kernel(
    float* __restrict__ a_out, const float* __restrict__ lr,
    const int* __restrict__ temp_p, int last)
{
    const int row  = blockIdx.x * 8 + (threadIdx.x >> 5);
    const int lane = threadIdx.x & 31;
    const size_t base = (size_t)row * NN + lane * 16;
    const float* Gr = g_G + base;

    float g[16];
#pragma unroll
    for (int q = 0; q < 4; q++) {
        float4 vg = *(const float4*)(Gr + q * 4);
        g[q * 4 + 0] = vg.x; g[q * 4 + 1] = vg.y; g[q * 4 + 2] = vg.z; g[q * 4 + 3] = vg.w;
    }

    union U16 { uint4 u4[2]; __nv_bfloat16 h[16]; };
    U16 uh, ul;
    uh.u4[0] = *(const uint4*)(g_ahh + base);
    uh.u4[1] = *(const uint4*)(g_ahh + base + 8);
    ul.u4[0] = *(const uint4*)(g_ahl + base);
    ul.u4[1] = *(const uint4*)(g_ahl + base + 8);

    float av[16];
#pragma unroll
    for (int c = 0; c < 16; c++)
        av[c] = __bfloat162float(uh.h[c]) + __bfloat162float(ul.h[c]);

    float p[16];
    float run = 0.f;
#pragma unroll
    for (int c = 0; c < 16; c++) { run += g[c]; p[c] = run; }
    float inc = run;
#pragma unroll
    for (int o = 1; o < 32; o <<= 1) {
        float n = __shfl_up_sync(0xffffffffu, inc, o);
        if (lane >= o) inc += n;
    }
    const float excl = inc - run;

    const float lr_abs = fabsf(lr[0]);
    const float invT   = 1.f / decode_scalar(temp_p);

    float lo[16];
    float mx = -INFINITY;
#pragma unroll
    for (int c = 0; c < 16; c++) {
        float cum = excl + p[c];
        float l = (av[c] - lr_abs * (g[c] - 2.f * cum)) * invT;
        lo[c] = l;
        mx = fmaxf(mx, l);
    }
#pragma unroll
    for (int o = 16; o > 0; o >>= 1) mx = fmaxf(mx, __shfl_xor_sync(0xffffffffu, mx, o));

    float s = 0.f;
#pragma unroll
    for (int c = 0; c < 16; c++) { lo[c] = __expf(lo[c] - mx); s += lo[c]; }
#pragma unroll
    for (int o = 16; o > 0; o >>= 1) s += __shfl_xor_sync(0xffffffffu, s, o);
    const float invS = 1.f / s;

    U16 oh, ol;
#pragma unroll
    for (int c = 0; c < 16; c++) {
        float v = lo[c] * invS;
        __nv_bfloat16 hi = __float2bfloat16(v);
        oh.h[c] = hi;
        ol.h[c] = __float2bfloat16(v - __bfloat162float(hi));
        lo[c] = v;
    }
    *(uint4*)(g_ahh + base)     = oh.u4[0];
    *(uint4*)(g_ahh + base + 8) = oh.u4[1];
    *(uint4*)(g_ahl + base)     = ol.u4[0];
    *(uint4*)(g_ahl + base + 8) = ol.u4[1];

    if (last) {
        float* ar = a_out + base;
#pragma unroll
        for (int q = 0; q < 4; q++)
            *(float4*)(ar + q * 4) = make_float4(lo[q * 4 + 0], lo[q * 4 + 1],
                                                 lo[q * 4 + 2], lo[q * 4 + 3]);
    }
}

// ---------------------------------------------------------------------------
// y[b,k] = sum_i x[b,i] * a[b,i,k]; 16 i-chunks per batch + atomicAdd.
// ---------------------------------------------------------------------------
__global__ void init_y_kernel(float* __restrict__ y)
{
    y[blockIdx.x * 1024 + threadIdx.x] = 0.f;
}

__global__ void __launch_bounds__(512) y_kernel(
    const float* __restrict__ x, const float* __restrict__ a, float* __restrict__ y)
{
    int b  = blockIdx.x;
    int ch = blockIdx.y;
    int k  = threadIdx.x;
    __shared__ float xs[32];
    if (k < 32) xs[k] = x[b * NN + ch * 32 + k];
    __syncthreads();
    const float* ab = a + (size_t)b * NN * NN + (size_t)ch * 32 * NN;
    float a0 = 0.f, a1 = 0.f, a2 = 0.f, a3 = 0.f;
#pragma unroll
    for (int i = 0; i < 32; i += 4) {
        a0 = fmaf(xs[i + 0], ab[(size_t)(i + 0) * NN + k], a0);
        a1 = fmaf(xs[i + 1], ab[(size_t)(i + 1) * NN + k], a1);
        a2 = fmaf(xs[i + 2], ab[(size_t)(i + 2) * NN + k], a2);
        a3 = fmaf(xs[i + 3], ab[(size_t)(i + 3) * NN + k], a3);
    }
    atomicAdd(&y[b * NN + k], (a0 + a1) + (a2 + a3));
}

// ---------------------------------------------------------------------------
extern "C" void kernel_launch(void* const* d_in, const int* in_sizes, int n_in,
                              void* d_out, int out_size)
{
    const float* x   = (const float*)d_in[0];
    const float* w1  = (const float*)d_in[1];
    const float* b1  = (const float*)d_in[2];
    const float* w2  = (const float*)d_in[3];
    // d_in[4] = b2 (cancels in c - c^T), d_in[6] = steps (fixed at 8)
    const float* lr  = (const float*)d_in[5];
    const int* temp_p = (const int*)d_in[7];

    float* y = (float*)d_out;              // (32,1,512)
    float* a = (float*)d_out + NB * NN;    // (32,512,512), written on last step

    cudaFuncSetAttribute(gemm_mma_kernel, cudaFuncAttributeMaxDynamicSharedMemorySize, GEMM_SMEM);

    compute_c_kernel<<<dim3(NN / 8, NB), 256>>>(x, w1, b1, w2);
    step0_kernel<<<NB * NN, 512>>>(lr, temp_p);

    for (int s = 0; s < 7; s++) {
        gemm_mma_kernel<<<dim3(4, 4, NB), 256, GEMM_SMEM>>>();
        epi_fuse_kernel<<<NB * NN / 8, 256>>>(a, lr, temp_p, (s == 6) ? 1 : 0);
    }

    init_y_kernel<<<NB * NN / 1024, 1024>>>(y);
    y_kernel<<<dim3(NB, 16), 512>>>(x, a, y);
}

// round 6
// speedup vs baseline: 5.7228x; 1.9149x over previous
#include <cuda_runtime.h>
#include <cuda_fp16.h>
#include <math.h>
#include <cstdint>

#define NB 32
#define NN 512

// Scratch (device globals; allocation-free per harness rules).
__device__ __align__(16) __half g_c16[(size_t)NB * NN * NN];  // fp16 c [m][k]
__device__ __align__(16) __half g_a16[(size_t)NB * NN * NN];  // fp16 a [j][n] row-major
__device__ __align__(16) float  g_G[(size_t)NB * NN * NN];    // G = c @ a (fp32)

// ---------------------------------------------------------------------------
__device__ __forceinline__ uint32_t smem_u32(const void* p) {
    uint32_t a;
    asm("{ .reg .u64 t; cvta.to.shared.u64 t, %1; cvt.u32.u64 %0, t; }" : "=r"(a) : "l"(p));
    return a;
}
__device__ __forceinline__ void cp_async16(uint32_t saddr, const void* gaddr) {
    asm volatile("cp.async.cg.shared.global [%0], [%1], 16;" :: "r"(saddr), "l"(gaddr) : "memory");
}
__device__ __forceinline__ void cp_commit() { asm volatile("cp.async.commit_group;" ::: "memory"); }
__device__ __forceinline__ void cp_wait3()  { asm volatile("cp.async.wait_group 3;" ::: "memory"); }
__device__ __forceinline__ void cp_wait0()  { asm volatile("cp.async.wait_group 0;" ::: "memory"); }
__device__ __forceinline__ void ldsm_x4(uint32_t* r, uint32_t addr) {
    asm volatile("ldmatrix.sync.aligned.m8n8.x4.shared.b16 {%0,%1,%2,%3}, [%4];"
                 : "=r"(r[0]), "=r"(r[1]), "=r"(r[2]), "=r"(r[3]) : "r"(addr));
}
__device__ __forceinline__ void ldsm_x4_t(uint32_t* r, uint32_t addr) {
    asm volatile("ldmatrix.sync.aligned.m8n8.x4.trans.shared.b16 {%0,%1,%2,%3}, [%4];"
                 : "=r"(r[0]), "=r"(r[1]), "=r"(r[2]), "=r"(r[3]) : "r"(addr));
}
__device__ __forceinline__ void mma_fp16(float* d, const uint32_t* a, const uint32_t* b) {
    asm volatile(
        "mma.sync.aligned.m16n8k16.row.col.f32.f16.f16.f32 "
        "{%0,%1,%2,%3}, {%4,%5,%6,%7}, {%8,%9}, {%0,%1,%2,%3};"
        : "+f"(d[0]), "+f"(d[1]), "+f"(d[2]), "+f"(d[3])
        : "r"(a[0]), "r"(a[1]), "r"(a[2]), "r"(a[3]), "r"(b[0]), "r"(b[1]));
}

// temp arrives as 1-elem scalar, int32 or float32 bits; decode robustly.
__device__ __forceinline__ float decode_scalar(const int* p) {
    int ib = *p;
    float f = __int_as_float(ib);
    if (isfinite(f) && fabsf(f) > 1e-30f && fabsf(f) < 1e30f) return f;
    return (float)ib;
}

// ---------------------------------------------------------------------------
// c[b,i,j]: 8 rows per block, 256 threads; fp16 store.
// ---------------------------------------------------------------------------
__global__ void __launch_bounds__(256) compute_c_kernel(
    const float* __restrict__ x, const float* __restrict__ w1,
    const float* __restrict__ b1, const float* __restrict__ w2)
{
    int b  = blockIdx.y;
    int i0 = blockIdx.x * 8;
    __shared__ float xs[NN];
    __shared__ float sw1a[16], sw1b[16], sb1[16], sw2[16];
    int t = threadIdx.x;
    if (t < 16) {
        sw1a[t] = w1[t * 2 + 0];
        sw1b[t] = w1[t * 2 + 1];
        sb1[t]  = b1[t];
        sw2[t]  = w2[t];
    }
    xs[t]       = x[b * NN + t];
    xs[t + 256] = x[b * NN + t + 256];
    __syncthreads();

    for (int ii = 0; ii < 8; ii++) {
        int i = i0 + ii;
        float xi = xs[i];
        size_t rowoff = ((size_t)b * NN + i) * NN;
        for (int j = t; j < NN; j += 256) {
            float xj = xs[j];
            float s = 0.f;
#pragma unroll
            for (int o = 0; o < 16; o++) {
                float h1 = fmaxf(fmaf(sw1a[o], xi, fmaf(sw1b[o], xj, sb1[o])), 0.f);
                float h2 = fmaxf(fmaf(sw1a[o], xj, fmaf(sw1b[o], xi, sb1[o])), 0.f);
                s = fmaf(sw2[o], h1 - h2, s);
            }
            g_c16[rowoff + j] = __float2half(s);
        }
    }
}

// ---------------------------------------------------------------------------
// Step 0 fused (a0 uniform). Writes a as fp16 row-major.
// ---------------------------------------------------------------------------
__global__ void __launch_bounds__(512) step0_kernel(
    const float* __restrict__ lr, const int* __restrict__ temp_p)
{
    const int row  = blockIdx.x;
    const int k    = threadIdx.x;
    const int lane = k & 31;
    const int wid  = k >> 5;
    size_t off = (size_t)row * NN + k;

    __shared__ float red[16];

    float v = __half2float(g_c16[off]);
#pragma unroll
    for (int o = 16; o > 0; o >>= 1) v += __shfl_xor_sync(0xffffffffu, v, o);
    if (lane == 0) red[wid] = v;
    __syncthreads();
    if (wid == 0) {
        float s = (lane < 16) ? red[lane] : 0.f;
#pragma unroll
        for (int o = 16; o > 0; o >>= 1) s += __shfl_xor_sync(0xffffffffu, s, o);
        if (lane == 0) red[0] = s;
    }
    __syncthreads();
    const float S = red[0];
    __syncthreads();

    const float lr_abs = fabsf(lr[0]);
    const float invT   = 1.f / decode_scalar(temp_p);
    const float invN   = 1.f / (float)NN;
    float logit = (invN - lr_abs * S * (1.f - (2.f * k + 1.f) * invN)) * invT;

    float m = logit;
#pragma unroll
    for (int o = 16; o > 0; o >>= 1) m = fmaxf(m, __shfl_xor_sync(0xffffffffu, m, o));
    if (lane == 0) red[wid] = m;
    __syncthreads();
    if (wid == 0) {
        float mm = (lane < 16) ? red[lane] : -INFINITY;
#pragma unroll
        for (int o = 16; o > 0; o >>= 1) mm = fmaxf(mm, __shfl_xor_sync(0xffffffffu, mm, o));
        if (lane == 0) red[0] = mm;
    }
    __syncthreads();
    m = red[0];
    __syncthreads();
    float e = __expf(logit - m);
    float s = e;
#pragma unroll
    for (int o = 16; o > 0; o >>= 1) s += __shfl_xor_sync(0xffffffffu, s, o);
    if (lane == 0) red[wid] = s;
    __syncthreads();
    if (wid == 0) {
        float ss = (lane < 16) ? red[lane] : 0.f;
#pragma unroll
        for (int o = 16; o > 0; o >>= 1) ss += __shfl_xor_sync(0xffffffffu, ss, o);
        if (lane == 0) red[0] = ss;
    }
    __syncthreads();
    g_a16[off] = __float2half(e / red[0]);
}

// ---------------------------------------------------------------------------
// Batched GEMM: G[b] = c[b] @ a[b], single-product fp16 mma.sync.
// 256 thr (8 warps: 4M x 2N, warp tile 32x64), block tile 128x128.
// 5-stage cp.async ring, K=16 per stage, prefetch distance 4.
// ---------------------------------------------------------------------------
#define PA 24                          // A smem pitch (fp16), 48 B rows
#define PB 136                         // B smem pitch (fp16), 272 B rows
#define A_TILE_B (128 * PA * 2)        // 6144 B
#define B_TILE_B (16 * PB * 2)         // 4352 B
#define STAGE_B  (A_TILE_B + B_TILE_B) // 10496
#define NSTAGE 5
#define GEMM_SMEM (NSTAGE * STAGE_B)   // 52480

__global__ void __launch_bounds__(256, 2) gemm_mma_kernel()
{
    extern __shared__ __align__(16) char sm[];
    const int b  = blockIdx.z;
    const int m0 = blockIdx.y * 128;
    const int n0 = blockIdx.x * 128;
    const int tid  = threadIdx.x;
    const int wid  = tid >> 5;
    const int lane = tid & 31;

    const __half* Amat = g_c16 + (size_t)b * NN * NN;
    const __half* Bmat = g_a16 + (size_t)b * NN * NN;

    const uint32_t smbase = smem_u32(sm);

    // per stage: A 128r x 16k (2 chunks/row) = 256 cp; B 16k x 128n = 256 cp;
    // 512 cp / 256 thr = 2 per thread.
    const int ar = tid >> 1;           // 0..127 A row
    const int ac = tid & 1;            // 16B chunk
    const int br = tid >> 4;           // 0..15 B k-row
    const int bc = tid & 15;           // 16B chunk
    auto load_stage = [&](int ks16) {
        const int k0 = ks16 * 16;
        const uint32_t sb = smbase + (ks16 % NSTAGE) * STAGE_B;
        cp_async16(sb + (uint32_t)(ar * (PA * 2) + ac * 16),
                   Amat + (size_t)(m0 + ar) * NN + k0 + ac * 8);
        cp_async16(sb + A_TILE_B + (uint32_t)(br * (PB * 2) + bc * 16),
                   Bmat + (size_t)(k0 + br) * NN + n0 + bc * 8);
        cp_commit();
    };

    const int wm = wid & 3;            // M quadrant (32 rows)
    const int wn = wid >> 2;           // N half (64 cols)

    float acc[2][8][4];
#pragma unroll
    for (int mi = 0; mi < 2; mi++)
#pragma unroll
        for (int ni = 0; ni < 8; ni++)
#pragma unroll
            for (int q = 0; q < 4; q++) acc[mi][ni][q] = 0.f;

    const int l_r = lane & 15;
    const int l_c = 8 * (lane >> 4);

#pragma unroll
    for (int s = 0; s < NSTAGE - 1; s++) load_stage(s);

    for (int s = 0; s < 32; s++) {
        cp_wait3();
        __syncthreads();

        const uint32_t sb = smbase + (s % NSTAGE) * STAGE_B;
        uint32_t ah[2][4];
#pragma unroll
        for (int mi = 0; mi < 2; mi++) {
            uint32_t addr = sb + (wm * 32 + mi * 16 + l_r) * (PA * 2) + l_c * 2;
            ldsm_x4(ah[mi], addr);
        }
        uint32_t bh[8][2];
#pragma unroll
        for (int nh = 0; nh < 2; nh++) {
#pragma unroll
            for (int t16 = 0; t16 < 2; t16++) {
                uint32_t addr = sb + A_TILE_B +
                                l_r * (PB * 2) + (wn * 64 + nh * 32 + t16 * 16 + l_c) * 2;
                uint32_t r4[4];
                ldsm_x4_t(r4, addr);
                int base = nh * 4 + t16 * 2;
                bh[base][0] = r4[0];     bh[base][1] = r4[1];
                bh[base + 1][0] = r4[2]; bh[base + 1][1] = r4[3];
            }
        }
#pragma unroll
        for (int mi = 0; mi < 2; mi++)
#pragma unroll
            for (int ni = 0; ni < 8; ni++)
                mma_fp16(acc[mi][ni], ah[mi], bh[ni]);

        if (s + NSTAGE - 1 < 32) load_stage(s + NSTAGE - 1);
    }
    cp_wait0();

    float* Gb = g_G + (size_t)b * NN * NN;
    const int g  = lane >> 2;
    const int t4 = lane & 3;
#pragma unroll
    for (int mi = 0; mi < 2; mi++) {
        int r0 = m0 + wm * 32 + mi * 16 + g;
#pragma unroll
        for (int ni = 0; ni < 8; ni++) {
            int col = n0 + wn * 64 + ni * 8 + t4 * 2;
            *(float2*)(Gb + (size_t)r0 * NN + col) =
                make_float2(acc[mi][ni][0], acc[mi][ni][1]);
            *(float2*)(Gb + (size_t)(r0 + 8) * NN + col) =
                make_float2(acc[mi][ni][2], acc[mi][ni][3]);
        }
    }
}

// ---------------------------------------------------------------------------
// Epilogue fused: warp per row; reads G + a(fp16); writes a' fp16
// (+ fp32 a' on last step).
// ---------------------------------------------------------------------------
__global__ void __launch_bounds__(256) epi_fuse_kernel(
    float* __restrict__ a_out, const float* __restrict__ lr,
    const int* __restrict__ temp_p, int last)
{
    const int row  = blockIdx.x * 8 + (threadIdx.x >> 5);
    const int lane = threadIdx.x & 31;
    const size_t base = (size_t)row * NN + lane * 16;
    const float* Gr = g_G + base;

    float g[16];
#pragma unroll
    for (int q = 0; q < 4; q++) {
        float4 vg = *(const float4*)(Gr + q * 4);
        g[q * 4 + 0] = vg.x; g[q * 4 + 1] = vg.y; g[q * 4 + 2] = vg.z; g[q * 4 + 3] = vg.w;
    }

    union U16 { uint4 u4[2]; __half h[16]; };
    U16 ua;
    ua.u4[0] = *(const uint4*)(g_a16 + base);
    ua.u4[1] = *(const uint4*)(g_a16 + base + 8);

    float av[16];
#pragma unroll
    for (int c = 0; c < 16; c++) av[c] = __half2float(ua.h[c]);

    float p[16];
    float run = 0.f;
#pragma unroll
    for (int c = 0; c < 16; c++) { run += g[c]; p[c] = run; }
    float inc = run;
#pragma unroll
    for (int o = 1; o < 32; o <<= 1) {
        float n = __shfl_up_sync(0xffffffffu, inc, o);
        if (lane >= o) inc += n;
    }
    const float excl = inc - run;

    const float lr_abs = fabsf(lr[0]);
    const float invT   = 1.f / decode_scalar(temp_p);

    float lo[16];
    float mx = -INFINITY;
#pragma unroll
    for (int c = 0; c < 16; c++) {
        float cum = excl + p[c];
        float l = (av[c] - lr_abs * (g[c] - 2.f * cum)) * invT;
        lo[c] = l;
        mx = fmaxf(mx, l);
    }
#pragma unroll
    for (int o = 16; o > 0; o >>= 1) mx = fmaxf(mx, __shfl_xor_sync(0xffffffffu, mx, o));

    float s = 0.f;
#pragma unroll
    for (int c = 0; c < 16; c++) { lo[c] = __expf(lo[c] - mx); s += lo[c]; }
#pragma unroll
    for (int o = 16; o > 0; o >>= 1) s += __shfl_xor_sync(0xffffffffu, s, o);
    const float invS = 1.f / s;

    U16 oa;
#pragma unroll
    for (int c = 0; c < 16; c++) {
        float v = lo[c] * invS;
        oa.h[c] = __float2half(v);
        lo[c] = v;
    }
    *(uint4*)(g_a16 + base)     = oa.u4[0];
    *(uint4*)(g_a16 + base + 8) = oa.u4[1];

    if (last) {
        float* ar = a_out + base;
#pragma unroll
        for (int q = 0; q < 4; q++)
            *(float4*)(ar + q * 4) = make_float4(lo[q * 4 + 0], lo[q * 4 + 1],
                                                 lo[q * 4 + 2], lo[q * 4 + 3]);
    }
}

// ---------------------------------------------------------------------------
// y[b,k] = sum_i x[b,i] * a[b,i,k]; 16 i-chunks per batch + atomicAdd.
// ---------------------------------------------------------------------------
__global__ void init_y_kernel(float* __restrict__ y)
{
    y[blockIdx.x * 1024 + threadIdx.x] = 0.f;
}

__global__ void __launch_bounds__(512) y_kernel(
    const float* __restrict__ x, const float* __restrict__ a, float* __restrict__ y)
{
    int b  = blockIdx.x;
    int ch = blockIdx.y;
    int k  = threadIdx.x;
    __shared__ float xs[32];
    if (k < 32) xs[k] = x[b * NN + ch * 32 + k];
    __syncthreads();
    const float* ab = a + (size_t)b * NN * NN + (size_t)ch * 32 * NN;
    float a0 = 0.f, a1 = 0.f, a2 = 0.f, a3 = 0.f;
#pragma unroll
    for (int i = 0; i < 32; i += 4) {
        a0 = fmaf(xs[i + 0], ab[(size_t)(i + 0) * NN + k], a0);
        a1 = fmaf(xs[i + 1], ab[(size_t)(i + 1) * NN + k], a1);
        a2 = fmaf(xs[i + 2], ab[(size_t)(i + 2) * NN + k], a2);
        a3 = fmaf(xs[i + 3], ab[(size_t)(i + 3) * NN + k], a3);
    }
    atomicAdd(&y[b * NN + k], (a0 + a1) + (a2 + a3));
}

// ---------------------------------------------------------------------------
extern "C" void kernel_launch(void* const* d_in, const int* in_sizes, int n_in,
                              void* d_out, int out_size)
{
    const float* x   = (const float*)d_in[0];
    const float* w1  = (const float*)d_in[1];
    const float* b1  = (const float*)d_in[2];
    const float* w2  = (const float*)d_in[3];
    // d_in[4] = b2 (cancels in c - c^T), d_in[6] = steps (fixed at 8)
    const float* lr  = (const float*)d_in[5];
    const int* temp_p = (const int*)d_in[7];

    float* y = (float*)d_out;              // (32,1,512)
    float* a = (float*)d_out + NB * NN;    // (32,512,512), written on last step

    cudaFuncSetAttribute(gemm_mma_kernel, cudaFuncAttributeMaxDynamicSharedMemorySize, GEMM_SMEM);

    compute_c_kernel<<<dim3(NN / 8, NB), 256>>>(x, w1, b1, w2);
    step0_kernel<<<NB * NN, 512>>>(lr, temp_p);

    for (int s = 0; s < 7; s++) {
        gemm_mma_kernel<<<dim3(4, 4, NB), 256, GEMM_SMEM>>>();
        epi_fuse_kernel<<<NB * NN / 8, 256>>>(a, lr, temp_p, (s == 6) ? 1 : 0);
    }

    init_y_kernel<<<NB * NN / 1024, 1024>>>(y);
    y_kernel<<<dim3(NB, 16), 512>>>(x, a, y);
}